// round 16
// baseline (speedup 1.0000x reference)
#include <cuda_runtime.h>
#include <cstdint>
#include <cstddef>

#define NS     730
#define NG     1000
#define MUc    8
#define NCHAIN 8000
#define TCHUNK 183          // ceil(732/4): 4-step chunks, padded to 732
#define PRECSf 1e-05f
#define XS     (NG*3)
#define PS     (NG*13*MUc)

__constant__ float LBc[13] = {1.0f, 50.0f, 0.05f, 0.01f, 0.001f, 0.2f, 0.0f, 0.0f, -2.5f, 0.5f, 0.0f, 0.0f, 0.3f};
__constant__ float UBc[13] = {6.0f, 1000.0f, 0.9f, 0.5f, 0.2f, 1.0f, 10.0f, 100.0f, 2.5f, 10.0f, 0.1f, 0.2f, 5.0f};

// Static scratch (zero-initialized at module load; pad rows never written stay 0).
__device__ float4 g_B   [TCHUNK * NCHAIN];   // [t4][chain] transformed BETA, 4 steps
__device__ float4 g_BT  [TCHUNK * NCHAIN];   // [t4][chain] transformed BETAET
__device__ float4 g_PTEL[732 * NG];          // [t][g] = (P, T, E, lg2(E))

__device__ __forceinline__ float fast_lg2(float a) {
    float r; asm("lg2.approx.f32 %0, %1;" : "=f"(r) : "f"(a)); return r;
}
__device__ __forceinline__ float fast_ex2(float a) {
    float r; asm("ex2.approx.f32 %0, %1;" : "=f"(r) : "f"(a)); return r;
}

// ============================================================================
// Repack kernels (verified in R11: total ~31 us)
// ============================================================================
__global__ void __launch_bounds__(256) repack_par(const float* __restrict__ par)
{
    int id = blockIdx.x * 256 + threadIdx.x;       // id = t4*NCHAIN + c
    if (id >= TCHUNK * NCHAIN) return;
    int t4 = id / NCHAIN;
    int c  = id - t4 * NCHAIN;
    int g = c >> 3, m = c & 7;
    const float dB  = UBc[0]  - LBc[0],  lbB  = LBc[0];
    const float dBT = UBc[12] - LBc[12], lbBT = LBc[12];
    float4 vb, vbt;
    float* pb  = (float*)&vb;
    float* pbt = (float*)&vbt;
    #pragma unroll
    for (int k = 0; k < 4; k++) {
        int t = t4 * 4 + k;
        float rB = 0.0f, rBT = 0.0f;
        if (t < NS) {
            size_t base = ((size_t)t * NG + g) * (13u * MUc) + m;
            rB  = par[base + 0*MUc];
            rBT = par[base + 12*MUc];
        }
        pb [k] = fmaf(rB,  dB,  lbB);
        pbt[k] = fmaf(rBT, dBT, lbBT);
    }
    g_B [id] = vb;
    g_BT[id] = vbt;
}

__global__ void __launch_bounds__(256) repack_x(const float* __restrict__ x)
{
    int id = blockIdx.x * 256 + threadIdx.x;       // id = t*NG + g
    if (id >= NS * NG) return;
    float P = x[(size_t)id*3 + 0];
    float T = x[(size_t)id*3 + 1];
    float E = x[(size_t)id*3 + 2];
    g_PTEL[id] = make_float4(P, T, E, fast_lg2(E));
}

// ============================================================================
// Main kernel
// ============================================================================
struct HC {
    float FC, K0, K1, K2, PERCc, UZL, TT, negCWH;
    float CFMAX, negCFMAXTT, negCFR;
    float neglgFC, neglgLPFC;
};

__device__ __forceinline__ float hbv_step(
    float& SP, float& MW, float& SM, float& SUZ, float& SLZ, const HC& c,
    float P_, float T_, float E_, float lgE, float BETA, float BETAET)
{
    float m0 = fmaf(c.CFMAX, T_, c.negCFMAXTT);      // CFMAX*(T-TT)
    float mm = fmaxf(m0, 0.0f);
    float rr = fmaxf(c.negCFR * m0, 0.0f);
    bool  wet = (T_ >= c.TT);
    float rain = wet ? P_ : 0.0f;
    float snow = wet ? 0.0f : P_;
    float C1 = BETA   * c.neglgFC;
    float C2 = fmaf(BETAET, c.neglgLPFC, lgE);
    // snow module (off critical chain)
    SP += snow;
    float melt = fminf(mm, SP);
    MW += melt; SP -= melt;
    float refr = fminf(rr, MW);
    SP += refr; MW -= refr;
    float tosoil = fmaxf(fmaf(c.negCWH, SP, MW), 0.0f);
    MW -= tosoil;
    float rt = rain + tosoil;
    // soil module — loop-carried critical chain
    float lgSM = fast_lg2(SM);
    float sw   = fast_ex2(fminf(fmaf(BETA, lgSM, C1), 0.0f));
    float recharge = rt * sw;
    float SM1 = (SM + rt) - recharge;
    float SM2 = fminf(SM1, c.FC);
    float excess = SM1 - SM2;
    float lgSM2 = fast_lg2(SM2);
    float ea    = fast_ex2(fmaf(BETAET, lgSM2, C2));   // E*(SM2/(LP*FC))^BETAET
    float ETact = fminf(fminf(SM2, E_), ea);
    SM = fmaxf(SM2 - ETact, PRECSf);
    // routing
    SUZ += recharge + excess;
    float PERC = fminf(SUZ, c.PERCc);
    SUZ -= PERC;
    float Q0 = c.K0 * fmaxf(SUZ - c.UZL, 0.0f);
    SUZ -= Q0;
    float Q1 = c.K1 * SUZ;
    SUZ -= Q1;
    SLZ += PERC;
    float Q2 = c.K2 * SLZ;
    SLZ -= Q2;
    return Q0 + Q1 + Q2;
}

// Generic fallback (any i0/i1) — correctness-only path.
__device__ void run_generic(
    const float* __restrict__ x, const float* __restrict__ par,
    float* __restrict__ out, int g, int m, int staind, int i0, int i1)
{
    float cp[13];
    {
        const float* pb = par + ((size_t)staind*NG + (size_t)g)*13u*MUc + m;
        #pragma unroll
        for (int p = 0; p < 13; p++)
            cp[p] = fmaf(pb[p*MUc], (UBc[p]-LBc[p]), LBc[p]);
    }
    const float lb0 = LBc[i0], d0 = UBc[i0]-LBc[i0];
    const float lb1 = LBc[i1], d1 = UBc[i1]-LBc[i1];
    const float* xp  = x   + (size_t)g*3;
    const float* pp0 = par + ((size_t)g*13 + (size_t)i0)*MUc + m;
    const float* pp1 = par + ((size_t)g*13 + (size_t)i1)*MUc + m;

    float SP=0.001f, MW=0.001f, SM=0.001f, SUZ=0.001f, SLZ=0.001f;
    const unsigned FULL = 0xffffffffu;

    for (int t = 0; t < NS; t++) {
        float P_ = xp[(long)t*XS + 0];
        float T_ = xp[(long)t*XS + 1];
        float E_ = xp[(long)t*XS + 2];
        float v0 = fmaf(pp0[(long)t*PS], d0, lb0);
        float v1 = fmaf(pp1[(long)t*PS], d1, lb1);
        float pr[13];
        #pragma unroll
        for (int p = 0; p < 13; p++) {
            float v = cp[p];
            if (p == i0) v = v0;
            if (p == i1) v = v1;
            pr[p] = v;
        }
        float BETA=pr[0], FC=pr[1], K0=pr[2], K1=pr[3], K2=pr[4], LP=pr[5],
              PERCc=pr[6], UZL=pr[7], TT=pr[8], CFMAX=pr[9], CFR=pr[10],
              CWH=pr[11], BETAET=pr[12];
        float rain = (T_ >= TT) ? P_ : 0.0f;
        float snow = P_ - rain;
        SP += snow;
        float melt = fminf(fmaxf(CFMAX*(T_-TT), 0.0f), SP);
        MW += melt; SP -= melt;
        float refr = fminf(fmaxf(CFR*CFMAX*(TT-T_), 0.0f), MW);
        SP += refr; MW -= refr;
        float tosoil = fmaxf(MW - CWH*SP, 0.0f);
        MW -= tosoil;
        float sw = fminf(fast_ex2(BETA*(fast_lg2(SM) - fast_lg2(FC))), 1.0f);
        float rt = rain + tosoil;
        float recharge = rt * sw;
        float SM1 = SM + rt - recharge;
        float excess = fmaxf(SM1 - FC, 0.0f);
        float SM2 = SM1 - excess;
        float ef = fminf(fast_ex2(BETAET*(fast_lg2(SM2) - fast_lg2(LP*FC))), 1.0f);
        float ETact = fminf(SM2, E_*ef);
        SM = fmaxf(SM2 - ETact, PRECSf);
        SUZ += recharge + excess;
        float PERC = fminf(SUZ, PERCc);
        SUZ -= PERC;
        float Q0 = K0 * fmaxf(SUZ - UZL, 0.0f);
        SUZ -= Q0;
        float Q1 = K1 * SUZ;
        SUZ -= Q1;
        SLZ += PERC;
        float Q2 = K2 * SLZ;
        SLZ -= Q2;
        float qv = Q0 + Q1 + Q2;
        qv += __shfl_xor_sync(FULL, qv, 1);
        qv += __shfl_xor_sync(FULL, qv, 2);
        qv += __shfl_xor_sync(FULL, qv, 4);
        if (m == 0) out[(size_t)t*NG + g] = qv * 0.125f;
    }
}

__global__ void __launch_bounds__(64, 1)
hbv_main(const float* __restrict__ x, const float* __restrict__ par,
         const int* __restrict__ staind_p, const int* __restrict__ tdlst_p,
         int n_td, float* __restrict__ out)
{
    int tid = blockIdx.x * 64 + threadIdx.x;   // 8000 threads exactly
    int g = tid >> 3, m = tid & 7;
    int staind = staind_p[0];
    int t0 = tdlst_p[0];
    int t1 = (n_td > 1) ? tdlst_p[1] : t0;
    int i0 = ((t0 - 1) % 13 + 13) % 13;
    int i1 = ((t1 - 1) % 13 + 13) % 13;
    if (!((i0 == 12 && i1 == 0) || (i0 == 0 && i1 == 12))) {
        run_generic(x, par, out, g, m, staind, i0, i1);
        return;
    }

    // ---- chain-constant parameters ----
    HC c;
    {
        const float* pb = par + ((size_t)staind*NG + (size_t)g)*13u*MUc + m;
        float cp[13];
        #pragma unroll
        for (int p = 0; p < 13; p++)
            cp[p] = fmaf(pb[p*MUc], (UBc[p]-LBc[p]), LBc[p]);
        c.FC = cp[1]; c.K0 = cp[2]; c.K1 = cp[3]; c.K2 = cp[4];
        c.PERCc = cp[6]; c.UZL = cp[7]; c.TT = cp[8]; c.negCWH = -cp[11];
        c.CFMAX = cp[9];
        c.negCFMAXTT = -cp[9]*cp[8];
        c.negCFR = -cp[10];
        c.neglgFC   = -fast_lg2(cp[1]);
        c.neglgLPFC = -fast_lg2(cp[5]*cp[1]);
    }

    float SP=0.001f, MW=0.001f, SM=0.001f, SUZ=0.001f, SLZ=0.001f;
    const unsigned FULL = 0xffffffffu;
    const bool hi4 = (m & 4) != 0, hi2 = (m & 2) != 0, h1 = (m & 1) != 0;

    const float4* pB  = g_B  + tid;       // +NCHAIN per batch
    const float4* pBT = g_BT + tid;
    const float4* pe  = g_PTEL + g;       // +4*NG per batch

    // pipeline: params distance 2; PTEL distance 1 (block-shared, L1-resident)
    float4 cB  = pB [0],       cBT  = pBT[0];
    float4 n1B = pB [NCHAIN],  n1BT = pBT[NCHAIN];
    float4 e0 = pe[0], e1 = pe[NG], e2 = pe[2*NG], e3 = pe[3*NG];

    for (int b = 0; b < TCHUNK; b++) {
        float4 n2B, n2BT, f0, f1, f2, f3;
        const bool pf2 = (b + 2 < TCHUNK);
        const bool pf1 = (b + 1 < TCHUNK);
        if (pf2) { n2B = pB[2*NCHAIN]; n2BT = pBT[2*NCHAIN]; }
        if (pf1) { f0 = pe[4*NG]; f1 = pe[5*NG]; f2 = pe[6*NG]; f3 = pe[7*NG]; }

        float q0 = hbv_step(SP,MW,SM,SUZ,SLZ,c, e0.x,e0.y,e0.z,e0.w, cB.x, cBT.x);
        float q1 = hbv_step(SP,MW,SM,SUZ,SLZ,c, e1.x,e1.y,e1.z,e1.w, cB.y, cBT.y);
        float q2 = hbv_step(SP,MW,SM,SUZ,SLZ,c, e2.x,e2.y,e2.z,e2.w, cB.z, cBT.z);
        float q3 = hbv_step(SP,MW,SM,SUZ,SLZ,c, e3.x,e3.y,e3.z,e3.w, cB.w, cBT.w);

        // reduce-scatter over 8-lane mu group: lane pair (2*hi4+hi2) owns its step
        float s1_0, s1_1;
        {
            float send0 = hi4 ? q0 : q2;
            float send1 = hi4 ? q1 : q3;
            float recv0 = __shfl_xor_sync(FULL, send0, 4);
            float recv1 = __shfl_xor_sync(FULL, send1, 4);
            s1_0 = (hi4 ? q2 : q0) + recv0;
            s1_1 = (hi4 ? q3 : q1) + recv1;
        }
        float s2;
        {
            float send = hi2 ? s1_0 : s1_1;
            float recv = __shfl_xor_sync(FULL, send, 2);
            s2 = (hi2 ? s1_1 : s1_0) + recv;
        }
        float tot = s2 + __shfl_xor_sync(FULL, s2, 1);
        int item = (hi4 ? 2 : 0) + (hi2 ? 1 : 0);
        int step = b*4 + item;
        if (!h1 && step < NS)
            out[(size_t)step*NG + g] = tot * 0.125f;

        // rotate pipeline
        cB = n1B; cBT = n1BT;
        if (pf2) { n1B = n2B; n1BT = n2BT; }
        if (pf1) { e0 = f0; e1 = f1; e2 = f2; e3 = f3; }
        pB += NCHAIN; pBT += NCHAIN; pe += 4*NG;
    }
}

extern "C" void kernel_launch(void* const* d_in, const int* in_sizes, int n_in,
                              void* d_out, int out_size)
{
    const float* x      = (const float*)d_in[0];   // (730, 1000, 3) f32
    const float* par    = (const float*)d_in[1];   // (730, 1000, 13, 8) f32
    const int*   staind = (const int*)d_in[2];     // scalar
    const int*   tdlst  = (const int*)d_in[3];     // (2,) int32
    int n_td = in_sizes[3];
    (void)n_in; (void)out_size;

    repack_par<<<(TCHUNK*NCHAIN + 255)/256, 256>>>(par);
    repack_x  <<<(NS*NG + 255)/256, 256>>>(x);
    hbv_main  <<<125, 64>>>(x, par, staind, tdlst, n_td, (float*)d_out);
}